// round 16
// baseline (speedup 1.0000x reference)
#include <cuda_runtime.h>
#include <stdint.h>

#define HH 512
#define WW 512
#define HW (HH*WW)
#define NS 8            // samples
#define NIMG 16         // samples * {pred, mask}
#define KP 1024         // points per set
#define T_MST 256
#define NPT 4           // nodes per MST thread
#define UMAXV 0xFFFFFFFFu
#define SENTX 46000u    // retired-node x (scaled); cands land in [8.79e8, 2.39e9]
#define SKIPTHR 0x20000000u  // 2^29: real keys <= 5.348e8 < 2^29; sentinel cands above
#define WPR 16          // 512/32 words per row

// ---------------- scratch (static device globals; no allocation) ----------------
__device__ unsigned g_mask[NIMG * 8192];          // binarized bitmasks (512x512 bits)
__device__ unsigned g_fbits[NIMG * 8192];         // lbp<THR flag bitmasks
__device__ float2   g_pts[NIMG][KP];              // selected points (r, c) float
__device__ int2     g_edges[NIMG][KP - 1];        // MST edges (src, j)
__device__ float    g_part[NIMG];                 // per-(sample,tree) partial norms
__device__ unsigned g_cnt;                        // loss completion counter

// ---------------- 1) binarize -> bitmasks ---------------------------------------
__global__ void binarize_kernel(const float* __restrict__ mo, const float* __restrict__ lb) {
    int gid = blockIdx.x * blockDim.x + threadIdx.x;   // exactly NS*HW threads
    if (gid == 0) g_cnt = 0u;                          // reset loss counter each call
    int s = gid >> 18;
    int p = gid & (HW - 1);
    unsigned bp = __ballot_sync(0xffffffffu, __ldg(mo + gid) > 0.0f);  // sigmoid>0.5 <=> x>0
    unsigned bm = __ballot_sync(0xffffffffu, __ldg(lb + gid) > 0.5f);
    if ((threadIdx.x & 31) == 0) {
        int w = p >> 5;
        g_mask[(2 * s)     * 8192 + w] = bp;
        g_mask[(2 * s + 1) * 8192 + w] = bm;
    }
}

// ---------------- 2) uniform LBP on bitmasks (exact) ----------------------------
__device__ __forceinline__ unsigned maj3(unsigned a, unsigned b, unsigned c) {
    return (a & b) | (c & (a ^ b));
}
__device__ __forceinline__ void sum8(const unsigned b[8],
                                     unsigned& s0, unsigned& s1, unsigned& s2, unsigned& s3) {
    unsigned t0 = b[0] ^ b[1], c0 = b[0] & b[1];
    unsigned t1 = b[2] ^ b[3], c1 = b[2] & b[3];
    unsigned t2 = b[4] ^ b[5], c2 = b[4] & b[5];
    unsigned t3 = b[6] ^ b[7], c3 = b[6] & b[7];
    unsigned u0 = t0 ^ t1, d0 = t0 & t1;
    unsigned u1 = t2 ^ t3, d1 = t2 & t3;
    s0 = u0 ^ u1;
    unsigned e0 = u0 & u1;
    unsigned p0 = c0 ^ c1 ^ c2, q0 = maj3(c0, c1, c2);
    unsigned p1 = c3 ^ d0 ^ d1, q1 = maj3(c3, d0, d1);
    s1 = p0 ^ p1 ^ e0;
    unsigned q2 = maj3(p0, p1, e0);
    s2 = q0 ^ q1 ^ q2;
    s3 = maj3(q0, q1, q2);
}

struct RowBits { unsigned C, Lc, Rc, QL, QR; };

__device__ __forceinline__ RowBits rowbits(const unsigned* __restrict__ M, int y, int w) {
    RowBits rb;
    unsigned c = __ldg(M + y * WPR + w);
    unsigned prev = (w > 0)   ? __ldg(M + y * WPR + w - 1) : 0u;
    unsigned next = (w < 15)  ? __ldg(M + y * WPR + w + 1) : 0u;
    unsigned Lc = (w > 0)  ? __funnelshift_l(prev, c, 1) : ((c << 1) | (c & 1u));
    unsigned Rc = (w < 15) ? __funnelshift_r(c, next, 1) : ((c >> 1) | (c & 0x80000000u));
    unsigned QL = Lc & c;
    if (w == 0) QL = (QL & ~1u) | (c & Rc & 1u);   // col0: quad cols {0,1}
    rb.C = c; rb.Lc = Lc; rb.Rc = Rc; rb.QL = QL; rb.QR = c & Rc;
    return rb;
}

__global__ void lbp_bits_kernel() {
    int gid = blockIdx.x * blockDim.x + threadIdx.x;   // NIMG*8192 threads
    int img = gid >> 13;
    int rem = gid & 8191;
    int r = rem >> 4;
    int w = rem & 15;
    const unsigned* __restrict__ M = g_mask + img * 8192;

    int rm = max(r - 1, 0);
    int rp = min(r + 1, HH - 1);
    RowBits Rr  = rowbits(M, r,  w);
    RowBits Rrp = rowbits(M, rp, w);
    RowBits Rpm0, Rpm1;         // row pair for dr = -0.707: {clamp(r-1), clamp(r-1)+1}
    if (r == 0) { Rpm0 = Rr; Rpm1 = Rrp; }
    else        { Rpm0 = rowbits(M, rm, w); Rpm1 = Rr; }
    unsigned Crm = (r == 0) ? Rr.C : Rpm0.C;   // C(clamp(r-1))

    unsigned b[8];
    b[0] = Rr.Rc;                 // (0, +1)
    b[2] = Crm;                   // (-1, 0)
    b[4] = Rr.Lc;                 // (0, -1)
    b[6] = Rrp.C;                 // (+1, 0)
    b[1] = Rpm0.QR & Rpm1.QR;     // (-.707, +.707)
    b[3] = Rpm0.QL & Rpm1.QL;     // (-.707, -.707)
    b[5] = Rr.QL & Rrp.QL;        // (+.707, -.707)
    b[7] = Rr.QR & Rrp.QR;        // (+.707, +.707)

    unsigned s0, s1, s2, s3;
    sum8(b, s0, s1, s2, s3);
    unsigned ok_s = ~(s3 | (s2 & (s1 | s0)));     // sum < 5

    unsigned ch[8];
#pragma unroll
    for (int k = 0; k < 8; k++) ch[k] = b[k] ^ b[(k + 7) & 7];
    unsigned c0, c1, c2, c3;
    sum8(ch, c0, c1, c2, c3);
    unsigned ok_ch = ~(c2 | c3);                  // changes <= 2 (changes is even)

    g_fbits[gid] = Rr.C & ok_s & ok_ch;           // center must be 1
}

// ---------------- 3) Prim's MST with fused ordered compaction --------------------
// Prologue (was select_kernel): thread t owns flag words [32t, 32t+32) -- 8
// coalesced uint4 loads; popc + warp scan + 8-entry offset scan; ordered
// emission straight into s_xy (pre-scaled packed) and g_pts. Identical point
// order / clipping / zero-padding semantics to the standalone kernel.
// MST core (R15, field-proven rel_err=0): coords scaled x32; key = dx^2+dy^2+idx
// == 1024*d2+idx (exact reference ordering & ties); real keys <= 5.348e8 < 2^29;
// retired nodes get px=SENTX, key forced to sentinel cand in [8.79e8, 2.39e9];
// warp skip: wm >= 2^29. Loop unrolled x2 with literal parities.
struct MstState {
    unsigned px[NPT], py[NPT], key[NPT];
    int src[NPT];
};

__device__ __forceinline__ void mst_body(
    MstState& st, bool& skip, unsigned& lmin, int& j, unsigned& jxy,
    unsigned* s_red_par, const unsigned* s_xy, int2* ep, int step,
    int base, int lane, int wrp)
{
    if (!skip) {                              // from previous redux result
        const int t = j - base;               // owner iff t in [0, NPT)
        int sA = (t == 1) ? st.src[1] : st.src[0];
        int sB = (t == 3) ? st.src[3] : st.src[2];
        int srcj = (t >= 2) ? sB : sA;

        const unsigned jx = jxy >> 16, jy = jxy & 0xffffu;
        lmin = UMAXV;
#pragma unroll
        for (int q = 0; q < NPT; q++) {
            bool own = (t == q);
            st.px[q] = own ? SENTX : st.px[q];    // sentinel coordinate
            unsigned dx = st.px[q] - jx, dy = st.py[q] - jy;
            unsigned cand = dx * dx + dy * dy + (unsigned)(base + q);
            // merged retire: owner unconditionally takes cand (>= SKIPTHR)
            bool upd = own | (cand < st.key[q]);  // strict <, keeps old src on tie
            st.key[q] = upd ? cand : st.key[q];
            st.src[q] = upd ? j : st.src[q];
            lmin = min(lmin, st.key[q]);
        }
        if ((unsigned)t < (unsigned)NPT)          // fire-and-forget, off the chain
            ep[step] = make_int2(srcj, j);
    }
    unsigned wm = __reduce_min_sync(0xffffffffu, lmin);
    skip = (wm >= SKIPTHR);                       // next-iter skip
    if (lane == 0) s_red_par[wrp] = wm;
    __syncthreads();
    uint4 A = *(const uint4*)&s_red_par[0];
    uint4 B = *(const uint4*)&s_red_par[4];
    unsigned gm = min(min(min(A.x, A.y), min(A.z, A.w)),
                      min(min(B.x, B.y), min(B.z, B.w)));
    j = (int)(gm & 1023u);
    jxy = s_xy[j];                                // prefetch for next iteration
}

__global__ void __launch_bounds__(T_MST) mst_kernel() {
    const int img = blockIdx.x;
    __shared__ unsigned s_xy[KP];
    __shared__ __align__(16) unsigned s_red[2][8];
    __shared__ int s_wtot[8];
    __shared__ int s_woff[8];

    const int tid = threadIdx.x;
    const int lane = tid & 31;
    const int wrp = tid >> 5;

    // ---------- fused ordered compaction ----------
    for (int i = tid; i < KP; i += T_MST) {
        s_xy[i] = 0u;                              // zero-pad (scaled packed (0,0))
        g_pts[img][i] = make_float2(0.0f, 0.0f);
    }
    const uint4* __restrict__ F4 = (const uint4*)(g_fbits + img * 8192);
    uint4 wv[8];
    int cnt = 0;
#pragma unroll
    for (int i = 0; i < 8; i++) {
        wv[i] = __ldg(F4 + tid * 8 + i);
        cnt += __popc(wv[i].x) + __popc(wv[i].y) + __popc(wv[i].z) + __popc(wv[i].w);
    }
    int incl = cnt;
#pragma unroll
    for (int d = 1; d < 32; d <<= 1) {
        int n = __shfl_up_sync(0xffffffffu, incl, d);
        if (lane >= d) incl += n;
    }
    if (lane == 31) s_wtot[wrp] = incl;
    __syncthreads();
    if (tid == 0) {
        int acc = 0;
#pragma unroll
        for (int i = 0; i < 8; i++) { s_woff[i] = acc; acc += s_wtot[i]; }
    }
    __syncthreads();
    {
        int rank = s_woff[wrp] + (incl - cnt);
        if (rank < KP && cnt > 0) {
#pragma unroll
            for (int i = 0; i < 8 && rank < KP; i++) {
                unsigned ws[4] = { wv[i].x, wv[i].y, wv[i].z, wv[i].w };
#pragma unroll
                for (int k = 0; k < 4 && rank < KP; k++) {
                    unsigned m = ws[k];
                    int pbase = (tid * 32 + i * 4 + k) << 5;
                    while (m && rank < KP) {
                        int b = __ffs(m) - 1;
                        m &= m - 1;
                        int pp = pbase + b;
                        int rr = pp >> 9, cc = pp & 511;
                        g_pts[img][rank] = make_float2((float)rr, (float)cc);
                        s_xy[rank] = (((unsigned)rr << 16) | (unsigned)cc) << 5;
                        rank++;
                    }
                }
            }
        }
    }
    __syncthreads();

    // ---------- MST core (R15) ----------
    MstState st;
    const int base = tid * NPT;
    {
        const unsigned xy0 = s_xy[0];
        const unsigned jx = xy0 >> 16, jy = xy0 & 0xffffu;
#pragma unroll
        for (int q = 0; q < NPT; q++) {
            unsigned v = s_xy[base + q];
            st.px[q] = v >> 16; st.py[q] = v & 0xffffu;
            unsigned dx = st.px[q] - jx, dy = st.py[q] - jy;
            st.key[q] = dx * dx + dy * dy + (unsigned)(base + q);
            st.src[q] = 0;
        }
    }
    if (tid == 0) { st.key[0] = UMAXV; st.px[0] = SENTX; }

    unsigned lmin = UMAXV;
#pragma unroll
    for (int q = 0; q < NPT; q++) lmin = min(lmin, st.key[q]);
    unsigned wm = __reduce_min_sync(0xffffffffu, lmin);
    bool skip = (wm >= SKIPTHR);                  // warp fully retired
    if (lane == 0) s_red[0][wrp] = wm;
    __syncthreads();
    uint4 A = *(const uint4*)&s_red[0][0];
    uint4 B = *(const uint4*)&s_red[0][4];
    unsigned gm = min(min(min(A.x, A.y), min(A.z, A.w)),
                      min(min(B.x, B.y), min(B.z, B.w)));
    int j = (int)(gm & 1023u);
    unsigned jxy = s_xy[j];                       // pipelined fetch

    int2* __restrict__ ep = g_edges[img];
    // 1023 steps total: 511 double-bodies (parities 1,0) + 1 tail (parity 1)
#pragma unroll 1
    for (int step = 0; step < KP - 2; step += 2) {
        mst_body(st, skip, lmin, j, jxy, s_red[1], s_xy, ep, step,     base, lane, wrp);
        mst_body(st, skip, lmin, j, jxy, s_red[0], s_xy, ep, step + 1, base, lane, wrp);
    }
    mst_body(st, skip, lmin, j, jxy, s_red[1], s_xy, ep, KP - 2, base, lane, wrp);
}

// ---------------- 4) per-(sample,tree) loss + fused final ------------------------
__device__ __forceinline__ float pdist2(float2 a, float2 b) {
    float dx = a.x - b.x, dy = a.y - b.y;
    return sqrtf(dx * dx + dy * dy);   // exact: integer d2 < 2^24
}

__global__ void __launch_bounds__(256) loss_kernel(float* __restrict__ out) {
    const int blk = blockIdx.x;        // 16 blocks: (sample s, tree t)
    const int s = blk >> 1;
    const int t = blk & 1;             // 0: pred-tree edges, 1: mask-tree edges
    const int tid = threadIdx.x;

    __shared__ float2 sPp[KP], sPm[KP];
    __shared__ float red[256];
    // coalesced staging of both point sets (16 KB)
    for (int i = tid; i < KP; i += 256) {
        sPp[i] = g_pts[2 * s][i];
        sPm[i] = g_pts[2 * s + 1][i];
    }
    __syncthreads();

    const int2* __restrict__ E = g_edges[2 * s + t];
    float acc = 0.0f;
    for (int e = tid; e < KP - 1; e += 256) {
        int2 ee = E[e];
        float d = pdist2(sPp[ee.x], sPp[ee.y]) - pdist2(sPm[ee.x], sPm[ee.y]);
        acc += d * d;
    }
    red[tid] = acc;
    __syncthreads();
#pragma unroll
    for (int w = 128; w; w >>= 1) {
        if (tid < w) red[tid] += red[tid + w];
        __syncthreads();
    }
    if (tid == 0) {
        g_part[blk] = sqrtf(red[0]);
        __threadfence();
        unsigned done = atomicAdd(&g_cnt, 1u);
        if (done == NIMG - 1) {                   // last block: fused final
            float tt = 0.0f;
#pragma unroll
            for (int i = 0; i < NIMG; i++) tt += g_part[i];
            out[0] = 0.1f * tt / 8.0f;
        }
    }
}

// ---------------- launch ----------------
extern "C" void kernel_launch(void* const* d_in, const int* in_sizes, int n_in,
                              void* d_out, int out_size) {
    const float* model_output = (const float*)d_in[1];
    const float* labels       = (const float*)d_in[2];
    float* out = (float*)d_out;

    binarize_kernel<<<(NS * HW) / 256, 256>>>(model_output, labels);
    lbp_bits_kernel<<<(NIMG * 8192) / 256, 256>>>();
    mst_kernel<<<NIMG, T_MST>>>();
    loss_kernel<<<NIMG, 256>>>(out);
}

// round 17
// speedup vs baseline: 1.0258x; 1.0258x over previous
#include <cuda_runtime.h>
#include <stdint.h>

#define HH 512
#define WW 512
#define HW (HH*WW)
#define NS 8            // samples
#define NIMG 16         // samples * {pred, mask}
#define KP 1024         // points per set
#define T_MST 256
#define NPT 4           // nodes per MST thread
#define UMAXV 0xFFFFFFFFu
#define SENTX 46000u    // retired-node x (scaled); cands land in [8.79e8, 2.39e9]
#define SKIPTHR 0x20000000u  // 2^29: real keys <= 5.348e8 < 2^29; sentinel cands above
#define WPR 16          // 512/32 words per row
#define LOSS_SEG 4      // segments per (sample,tree) pair
#define LOSS_BLKS (NIMG * LOSS_SEG)   // 64

// ---------------- scratch (static device globals; no allocation) ----------------
__device__ unsigned g_mask[NIMG * 8192];          // binarized bitmasks (512x512 bits)
__device__ unsigned g_fbits[NIMG * 8192];         // lbp<THR flag bitmasks
__device__ float2   g_pts[NIMG][KP];              // selected points (r, c) float
__device__ unsigned g_pti[NIMG][KP];              // packed int coords (r<<16)|c
__device__ int2     g_edges[NIMG][KP - 1];        // MST edges (src, j)
__device__ float    g_pp[LOSS_BLKS];              // per-(pair,segment) partial sums
__device__ unsigned g_cnt;                        // loss completion counter

// ---------------- 1) binarize -> bitmasks ---------------------------------------
__global__ void binarize_kernel(const float* __restrict__ mo, const float* __restrict__ lb) {
    int gid = blockIdx.x * blockDim.x + threadIdx.x;   // exactly NS*HW threads
    if (gid == 0) g_cnt = 0u;                          // reset loss counter each call
    int s = gid >> 18;
    int p = gid & (HW - 1);
    unsigned bp = __ballot_sync(0xffffffffu, __ldg(mo + gid) > 0.0f);  // sigmoid>0.5 <=> x>0
    unsigned bm = __ballot_sync(0xffffffffu, __ldg(lb + gid) > 0.5f);
    if ((threadIdx.x & 31) == 0) {
        int w = p >> 5;
        g_mask[(2 * s)     * 8192 + w] = bp;
        g_mask[(2 * s + 1) * 8192 + w] = bm;
    }
}

// ---------------- 2) uniform LBP on bitmasks (exact) ----------------------------
__device__ __forceinline__ unsigned maj3(unsigned a, unsigned b, unsigned c) {
    return (a & b) | (c & (a ^ b));
}
__device__ __forceinline__ void sum8(const unsigned b[8],
                                     unsigned& s0, unsigned& s1, unsigned& s2, unsigned& s3) {
    unsigned t0 = b[0] ^ b[1], c0 = b[0] & b[1];
    unsigned t1 = b[2] ^ b[3], c1 = b[2] & b[3];
    unsigned t2 = b[4] ^ b[5], c2 = b[4] & b[5];
    unsigned t3 = b[6] ^ b[7], c3 = b[6] & b[7];
    unsigned u0 = t0 ^ t1, d0 = t0 & t1;
    unsigned u1 = t2 ^ t3, d1 = t2 & t3;
    s0 = u0 ^ u1;
    unsigned e0 = u0 & u1;
    unsigned p0 = c0 ^ c1 ^ c2, q0 = maj3(c0, c1, c2);
    unsigned p1 = c3 ^ d0 ^ d1, q1 = maj3(c3, d0, d1);
    s1 = p0 ^ p1 ^ e0;
    unsigned q2 = maj3(p0, p1, e0);
    s2 = q0 ^ q1 ^ q2;
    s3 = maj3(q0, q1, q2);
}

struct RowBits { unsigned C, Lc, Rc, QL, QR; };

__device__ __forceinline__ RowBits rowbits(const unsigned* __restrict__ M, int y, int w) {
    RowBits rb;
    unsigned c = __ldg(M + y * WPR + w);
    unsigned prev = (w > 0)   ? __ldg(M + y * WPR + w - 1) : 0u;
    unsigned next = (w < 15)  ? __ldg(M + y * WPR + w + 1) : 0u;
    unsigned Lc = (w > 0)  ? __funnelshift_l(prev, c, 1) : ((c << 1) | (c & 1u));
    unsigned Rc = (w < 15) ? __funnelshift_r(c, next, 1) : ((c >> 1) | (c & 0x80000000u));
    unsigned QL = Lc & c;
    if (w == 0) QL = (QL & ~1u) | (c & Rc & 1u);   // col0: quad cols {0,1}
    rb.C = c; rb.Lc = Lc; rb.Rc = Rc; rb.QL = QL; rb.QR = c & Rc;
    return rb;
}

__global__ void lbp_bits_kernel() {
    int gid = blockIdx.x * blockDim.x + threadIdx.x;   // NIMG*8192 threads
    int img = gid >> 13;
    int rem = gid & 8191;
    int r = rem >> 4;
    int w = rem & 15;
    const unsigned* __restrict__ M = g_mask + img * 8192;

    int rm = max(r - 1, 0);
    int rp = min(r + 1, HH - 1);
    RowBits Rr  = rowbits(M, r,  w);
    RowBits Rrp = rowbits(M, rp, w);
    RowBits Rpm0, Rpm1;         // row pair for dr = -0.707: {clamp(r-1), clamp(r-1)+1}
    if (r == 0) { Rpm0 = Rr; Rpm1 = Rrp; }
    else        { Rpm0 = rowbits(M, rm, w); Rpm1 = Rr; }
    unsigned Crm = (r == 0) ? Rr.C : Rpm0.C;   // C(clamp(r-1))

    unsigned b[8];
    b[0] = Rr.Rc;                 // (0, +1)
    b[2] = Crm;                   // (-1, 0)
    b[4] = Rr.Lc;                 // (0, -1)
    b[6] = Rrp.C;                 // (+1, 0)
    b[1] = Rpm0.QR & Rpm1.QR;     // (-.707, +.707)
    b[3] = Rpm0.QL & Rpm1.QL;     // (-.707, -.707)
    b[5] = Rr.QL & Rrp.QL;        // (+.707, -.707)
    b[7] = Rr.QR & Rrp.QR;        // (+.707, +.707)

    unsigned s0, s1, s2, s3;
    sum8(b, s0, s1, s2, s3);
    unsigned ok_s = ~(s3 | (s2 & (s1 | s0)));     // sum < 5

    unsigned ch[8];
#pragma unroll
    for (int k = 0; k < 8; k++) ch[k] = b[k] ^ b[(k + 7) & 7];
    unsigned c0, c1, c2, c3;
    sum8(ch, c0, c1, c2, c3);
    unsigned ok_ch = ~(c2 | c3);                  // changes <= 2 (changes is even)

    g_fbits[gid] = Rr.C & ok_s & ok_ch;           // center must be 1
}

// ---------------- 3) ordered compaction from flag bitmask ------------------------
__global__ void __launch_bounds__(1024) select_kernel() {
    const int img = blockIdx.x;
    __shared__ int s_wtot[32];
    __shared__ int s_woff[32];
    const int tid = threadIdx.x, lane = tid & 31, wrp = tid >> 5;

    g_pts[img][tid] = make_float2(0.0f, 0.0f);    // zero-pad
    g_pti[img][tid] = 0u;

    const unsigned* __restrict__ F = g_fbits + img * 8192;
    unsigned wv[8];
    int cnt = 0;
    const int w0 = tid * 8;
#pragma unroll
    for (int i = 0; i < 8; i++) { wv[i] = __ldg(F + w0 + i); cnt += __popc(wv[i]); }

    // block-wide exclusive prefix
    int incl = cnt;
#pragma unroll
    for (int d = 1; d < 32; d <<= 1) {
        int n = __shfl_up_sync(0xffffffffu, incl, d);
        if (lane >= d) incl += n;
    }
    if (lane == 31) s_wtot[wrp] = incl;
    __syncthreads();
    if (wrp == 0) {
        int t = s_wtot[lane];
        int ti = t;
#pragma unroll
        for (int d = 1; d < 32; d <<= 1) {
            int n = __shfl_up_sync(0xffffffffu, ti, d);
            if (lane >= d) ti += n;
        }
        s_woff[lane] = ti - t;
    }
    __syncthreads();
    int rank = s_woff[wrp] + (incl - cnt);

    if (rank < KP && cnt > 0) {
#pragma unroll
        for (int i = 0; i < 8; i++) {
            unsigned m = wv[i];
            int pbase = (w0 + i) << 5;
            while (m && rank < KP) {
                int b = __ffs(m) - 1;
                m &= m - 1;
                int pp = pbase + b;
                int rr = pp >> 9, cc = pp & 511;
                g_pts[img][rank] = make_float2((float)rr, (float)cc);
                g_pti[img][rank] = ((unsigned)rr << 16) | (unsigned)cc;
                rank++;
            }
            if (rank >= KP) break;
        }
    }
}

// ---------------- 4) Prim's MST: 256x4, unrolled x2 with static parities (R15) ---
// Exactness invariants (all field-proven rel_err=0): coords scaled x32, key =
// dx^2+dy^2+idx == 1024*d2+idx (identical ordering/ties to reference float-sqrt
// argmin); real keys <= 5.348e8 < 2^29; retired nodes get px=SENTX and key
// forced to the sentinel candidate in [8.79e8, 2.39e9] -- never wins. Warp skip:
// wm >= 2^29 <=> all 128 owned nodes retired. Loop unrolled by 2 with LITERAL
// parity indices (s_red[1], s_red[0]) -- halves loop control, removes par math.
struct MstState {
    unsigned px[NPT], py[NPT], key[NPT];
    int src[NPT];
};

__device__ __forceinline__ void mst_body(
    MstState& st, bool& skip, unsigned& lmin, int& j, unsigned& jxy,
    unsigned* s_red_par, const unsigned* s_xy, int2* ep, int step,
    int base, int lane, int wrp)
{
    if (!skip) {                              // from previous redux result
        const int t = j - base;               // owner iff t in [0, NPT)
        int sA = (t == 1) ? st.src[1] : st.src[0];
        int sB = (t == 3) ? st.src[3] : st.src[2];
        int srcj = (t >= 2) ? sB : sA;

        const unsigned jx = jxy >> 16, jy = jxy & 0xffffu;
        lmin = UMAXV;
#pragma unroll
        for (int q = 0; q < NPT; q++) {
            bool own = (t == q);
            st.px[q] = own ? SENTX : st.px[q];    // sentinel coordinate
            unsigned dx = st.px[q] - jx, dy = st.py[q] - jy;
            unsigned cand = dx * dx + dy * dy + (unsigned)(base + q);
            // merged retire: owner unconditionally takes cand (>= SKIPTHR)
            bool upd = own | (cand < st.key[q]);  // strict <, keeps old src on tie
            st.key[q] = upd ? cand : st.key[q];
            st.src[q] = upd ? j : st.src[q];
            lmin = min(lmin, st.key[q]);
        }
        if ((unsigned)t < (unsigned)NPT)          // fire-and-forget, off the chain
            ep[step] = make_int2(srcj, j);
    }
    unsigned wm = __reduce_min_sync(0xffffffffu, lmin);
    skip = (wm >= SKIPTHR);                       // next-iter skip
    if (lane == 0) s_red_par[wrp] = wm;
    __syncthreads();
    uint4 A = *(const uint4*)&s_red_par[0];
    uint4 B = *(const uint4*)&s_red_par[4];
    unsigned gm = min(min(min(A.x, A.y), min(A.z, A.w)),
                      min(min(B.x, B.y), min(B.z, B.w)));
    j = (int)(gm & 1023u);
    jxy = s_xy[j];                                // prefetch for next iteration
}

__global__ void __launch_bounds__(T_MST) mst_kernel() {
    const int img = blockIdx.x;
    __shared__ unsigned s_xy[KP];
    __shared__ __align__(16) unsigned s_red[2][8];

    const int tid = threadIdx.x;
    const int lane = tid & 31;
    const int wrp = tid >> 5;

    for (int i = tid; i < KP; i += T_MST) s_xy[i] = g_pti[img][i] << 5;  // scaled packed
    __syncthreads();

    MstState st;
    const int base = tid * NPT;
    {
        const unsigned xy0 = s_xy[0];
        const unsigned jx = xy0 >> 16, jy = xy0 & 0xffffu;
#pragma unroll
        for (int q = 0; q < NPT; q++) {
            unsigned v = s_xy[base + q];
            st.px[q] = v >> 16; st.py[q] = v & 0xffffu;
            unsigned dx = st.px[q] - jx, dy = st.py[q] - jy;
            st.key[q] = dx * dx + dy * dy + (unsigned)(base + q);
            st.src[q] = 0;
        }
    }
    if (tid == 0) { st.key[0] = UMAXV; st.px[0] = SENTX; }

    unsigned lmin = UMAXV;
#pragma unroll
    for (int q = 0; q < NPT; q++) lmin = min(lmin, st.key[q]);
    unsigned wm = __reduce_min_sync(0xffffffffu, lmin);
    bool skip = (wm >= SKIPTHR);                  // warp fully retired
    if (lane == 0) s_red[0][wrp] = wm;
    __syncthreads();
    uint4 A = *(const uint4*)&s_red[0][0];
    uint4 B = *(const uint4*)&s_red[0][4];
    unsigned gm = min(min(min(A.x, A.y), min(A.z, A.w)),
                      min(min(B.x, B.y), min(B.z, B.w)));
    int j = (int)(gm & 1023u);
    unsigned jxy = s_xy[j];                       // pipelined fetch

    int2* __restrict__ ep = g_edges[img];
    // 1023 steps total: 511 double-bodies (parities 1,0) + 1 tail (parity 1)
#pragma unroll 1
    for (int step = 0; step < KP - 2; step += 2) {
        mst_body(st, skip, lmin, j, jxy, s_red[1], s_xy, ep, step,     base, lane, wrp);
        mst_body(st, skip, lmin, j, jxy, s_red[0], s_xy, ep, step + 1, base, lane, wrp);
    }
    mst_body(st, skip, lmin, j, jxy, s_red[1], s_xy, ep, KP - 2, base, lane, wrp);
}

// ---------------- 5) loss: 64 segment blocks + deterministic last-block final ----
__device__ __forceinline__ float pdist2(float2 a, float2 b) {
    float dx = a.x - b.x, dy = a.y - b.y;
    return sqrtf(dx * dx + dy * dy);   // exact: integer d2 < 2^24
}

__global__ void __launch_bounds__(256) loss_kernel(float* __restrict__ out) {
    const int blk = blockIdx.x;            // 64 blocks: pair (0..15) x segment (0..3)
    const int pair = blk >> 2;
    const int seg = blk & 3;
    const int s = pair >> 1;
    const int t = pair & 1;                // 0: pred-tree edges, 1: mask-tree edges
    const int tid = threadIdx.x;

    const float2* __restrict__ Pp = g_pts[2 * s];
    const float2* __restrict__ Pm = g_pts[2 * s + 1];
    const int2*   __restrict__ E  = g_edges[2 * s + t];

    // one edge per thread (segment 3 drops edge 1023 which doesn't exist)
    const int e = seg * 256 + tid;
    float v = 0.0f;
    if (e < KP - 1) {
        int2 ee = __ldg(E + e);
        float2 pa = __ldg(&Pp[ee.x]), pb = __ldg(&Pp[ee.y]);
        float2 ma = __ldg(&Pm[ee.x]), mb = __ldg(&Pm[ee.y]);
        float d = pdist2(pa, pb) - pdist2(ma, mb);
        v = d * d;
    }
    __shared__ float red[256];
    red[tid] = v;
    __syncthreads();
#pragma unroll
    for (int w = 128; w; w >>= 1) {
        if (tid < w) red[tid] += red[tid + w];
        __syncthreads();
    }
    if (tid == 0) {
        g_pp[blk] = red[0];
        __threadfence();
        unsigned done = atomicAdd(&g_cnt, 1u);
        if (done == LOSS_BLKS - 1) {       // last block: deterministic final fold
            float tt = 0.0f;
#pragma unroll
            for (int p = 0; p < NIMG; p++) {
                float ps = ((g_pp[4 * p] + g_pp[4 * p + 1]) +
                            (g_pp[4 * p + 2] + g_pp[4 * p + 3]));
                tt += sqrtf(ps);
            }
            out[0] = 0.1f * tt / 8.0f;
        }
    }
}

// ---------------- launch ----------------
extern "C" void kernel_launch(void* const* d_in, const int* in_sizes, int n_in,
                              void* d_out, int out_size) {
    const float* model_output = (const float*)d_in[1];
    const float* labels       = (const float*)d_in[2];
    float* out = (float*)d_out;

    binarize_kernel<<<(NS * HW) / 256, 256>>>(model_output, labels);
    lbp_bits_kernel<<<(NIMG * 8192) / 256, 256>>>();
    select_kernel<<<NIMG, 1024>>>();
    mst_kernel<<<NIMG, T_MST>>>();
    loss_kernel<<<LOSS_BLKS, 256>>>(out);
}